// round 3
// baseline (speedup 1.0000x reference)
#include <cuda_runtime.h>
#include <cuda_bf16.h>
#include <math.h>

#define T_ 16
#define B_ 32
#define S_ 256
#define H_ 256
#define E_ 300
#define V_ 1000

// ---------------- scratch arena (floats) ----------------
#define OFF_EMB     0           // 512*300
#define OFF_XPROJ   153600      // 512*1024
#define OFF_GATES   677888      // 32*1024
#define OFF_H       710656      // 32*256
#define OFF_C       718848      // 32*256
#define OFF_ENCT    727040      // 8192*256
#define OFF_DECT    2824192     // 512*256
#define OFF_ATT     2955264     // 32*16*256
#define OFF_COMB    3086336     // 512*512
#define OFF_LOGITS  3348480     // 512*1000
#define SCRATCH_N   3860480

__device__ float g_scratch[SCRATCH_N];

// ---------------- embedding gather ----------------
__global__ void gather_emb_k(const int* __restrict__ tv,
                             const float* __restrict__ emb,
                             float* __restrict__ out) {
    int tb = blockIdx.x;                     // 0..T*B-1, row-major [T,B]
    int v = tv[tb];
    for (int e = threadIdx.x; e < E_; e += blockDim.x)
        out[tb * E_ + e] = emb[v * E_ + e];
}

// ---------------- generic C[M,N] = A[M,K]*B[N,K]^T + bias ----------------
// BM=BN=64, BK=16, 256 threads, 4x4 register tile per thread.
__global__ void sgemm_tn_k(const float* __restrict__ A, int lda,
                           const float* __restrict__ Bm,   // [N,K] row-major
                           const float* __restrict__ bias, // or nullptr
                           float* __restrict__ C, int ldc,
                           int M, int N, int K) {
    __shared__ float As[16][64];   // [kk][row]
    __shared__ float Bs[16][64];   // [kk][col]
    int tid = threadIdx.x;
    int tx = tid & 15;             // 0..15
    int ty = tid >> 4;             // 0..15
    int m0 = blockIdx.y * 64, n0 = blockIdx.x * 64;
    int row0 = ty * 4, col0 = tx * 4;

    float acc[4][4] = {};
    int lkk = tid & 15;
    int lr0 = tid >> 4;

    for (int k0 = 0; k0 < K; k0 += 16) {
        #pragma unroll
        for (int p = 0; p < 4; p++) {
            int r = lr0 + p * 16;
            int gk = k0 + lkk;
            int gm = m0 + r;
            As[lkk][r] = (gm < M && gk < K) ? A[(long)gm * lda + gk] : 0.f;
            int gn = n0 + r;
            Bs[lkk][r] = (gn < N && gk < K) ? Bm[(long)gn * K + gk] : 0.f;
        }
        __syncthreads();
        #pragma unroll
        for (int kk = 0; kk < 16; kk++) {
            float4 a4 = *reinterpret_cast<const float4*>(&As[kk][row0]);
            float4 b4 = *reinterpret_cast<const float4*>(&Bs[kk][col0]);
            float a[4] = {a4.x, a4.y, a4.z, a4.w};
            float b[4] = {b4.x, b4.y, b4.z, b4.w};
            #pragma unroll
            for (int i = 0; i < 4; i++)
                #pragma unroll
                for (int j = 0; j < 4; j++)
                    acc[i][j] += a[i] * b[j];
        }
        __syncthreads();
    }
    #pragma unroll
    for (int i = 0; i < 4; i++) {
        int gm = m0 + row0 + i;
        if (gm >= M) continue;
        #pragma unroll
        for (int j = 0; j < 4; j++) {
            int gn = n0 + col0 + j;
            if (gn >= N) continue;
            float v = acc[i][j];
            if (bias) v += bias[gn];
            C[(long)gm * ldc + gn] = v;
        }
    }
}

// ---------------- LSTM pointwise step ----------------
// gates_lin = h_{t-1} @ W_hh^T (no bias); xproj_t already has b_ih.
__global__ void lstm_point_k(const float* __restrict__ xproj_t,  // [B,4H]
                             const float* __restrict__ gates,    // [B,4H]
                             const float* __restrict__ b_hh,     // [4H]
                             float* __restrict__ h,              // [B,H]
                             float* __restrict__ c,              // [B,H]
                             float* __restrict__ comb_t) {       // combined + t*B*2H
    int b = blockIdx.x;
    int hh = threadIdx.x;
    int base = b * 4 * H_;
    float gi = xproj_t[base + hh]          + gates[base + hh]          + b_hh[hh];
    float gf = xproj_t[base + H_ + hh]     + gates[base + H_ + hh]     + b_hh[H_ + hh];
    float gg = xproj_t[base + 2 * H_ + hh] + gates[base + 2 * H_ + hh] + b_hh[2 * H_ + hh];
    float go = xproj_t[base + 3 * H_ + hh] + gates[base + 3 * H_ + hh] + b_hh[3 * H_ + hh];
    float cc = c[b * H_ + hh];
    float si = 1.f / (1.f + expf(-gi));
    float sf = 1.f / (1.f + expf(-gf));
    float so = 1.f / (1.f + expf(-go));
    cc = sf * cc + si * tanhf(gg);
    float hn = so * tanhf(cc);
    c[b * H_ + hh] = cc;
    h[b * H_ + hh] = hn;
    comb_t[b * (2 * H_) + H_ + hh] = hn;   // outs slot of combined
}

// ---------------- attention scores ----------------
// scores[b,t,s] = sum_h tanh(enc_t[s,b,h] + dec_t[t,b,h]) * wa[h] + ba
__global__ void attn_scores_k(const float* __restrict__ enc_t,
                              const float* __restrict__ dec_t,
                              const float* __restrict__ wa,
                              const float* __restrict__ ba,
                              float* __restrict__ att) {
    int b = blockIdx.x % B_;
    int t = blockIdx.x / B_;
    __shared__ float dec_sh[H_];
    __shared__ float wa_sh[H_];
    for (int hh = threadIdx.x; hh < H_; hh += blockDim.x) {
        dec_sh[hh] = dec_t[(t * B_ + b) * H_ + hh];
        wa_sh[hh] = wa[hh];
    }
    __syncthreads();
    float bav = ba[0];
    int warp = threadIdx.x >> 5, lane = threadIdx.x & 31;
    for (int s = warp; s < S_; s += 8) {
        const float* er = enc_t + (long)(s * B_ + b) * H_;
        float sum = 0.f;
        #pragma unroll 4
        for (int hh = lane; hh < H_; hh += 32)
            sum += tanhf(er[hh] + dec_sh[hh]) * wa_sh[hh];
        #pragma unroll
        for (int o = 16; o; o >>= 1) sum += __shfl_xor_sync(0xffffffffu, sum, o);
        if (lane == 0) att[(b * T_ + t) * S_ + s] = sum + bav;
    }
}

// ---------------- masked softmax over S (row of 256) ----------------
__global__ void softmax_att_k(float* __restrict__ att, const int* __restrict__ lens) {
    int bt = blockIdx.x;           // b*T + t
    int b = bt / T_;
    int s = threadIdx.x;           // 256
    __shared__ float red[S_];
    float v = att[bt * S_ + s];
    if (s >= lens[b]) v = -1e30f;
    red[s] = v; __syncthreads();
    for (int o = 128; o; o >>= 1) { if (s < o) red[s] = fmaxf(red[s], red[s + o]); __syncthreads(); }
    float m = red[0]; __syncthreads();
    float e = expf(v - m);
    red[s] = e; __syncthreads();
    for (int o = 128; o; o >>= 1) { if (s < o) red[s] += red[s + o]; __syncthreads(); }
    att[bt * S_ + s] = e * (1.f / red[0]);
}

// ---------------- context = att @ enc ----------------
__global__ void context_k(const float* __restrict__ att,
                          const float* __restrict__ enc,   // [S,B,H]
                          float* __restrict__ comb,        // [T,B,2H]
                          float* __restrict__ ctx_out) {   // [B,T,H]
    int bt = blockIdx.x;
    int b = bt / T_, t = bt % T_;
    __shared__ float a_sh[S_];
    a_sh[threadIdx.x] = att[bt * S_ + threadIdx.x];
    __syncthreads();
    int hh = threadIdx.x;
    float sum = 0.f;
    #pragma unroll 4
    for (int s = 0; s < S_; s++)
        sum = fmaf(a_sh[s], enc[(long)(s * B_ + b) * H_ + hh], sum);
    comb[(t * B_ + b) * (2 * H_) + hh] = sum;
    ctx_out[(b * T_ + t) * H_ + hh] = sum;
}

// ---------------- softmax over V=1000 ----------------
__global__ void softmax_v_k(const float* __restrict__ logits, float* __restrict__ out) {
    int tb = blockIdx.x;
    int tid = threadIdx.x;
    __shared__ float red[256];
    const float* row = logits + (long)tb * V_;
    float m = -1e30f;
    for (int v = tid; v < V_; v += 256) m = fmaxf(m, row[v]);
    red[tid] = m; __syncthreads();
    for (int o = 128; o; o >>= 1) { if (tid < o) red[tid] = fmaxf(red[tid], red[tid + o]); __syncthreads(); }
    m = red[0]; __syncthreads();
    float sum = 0.f;
    for (int v = tid; v < V_; v += 256) {
        float e = expf(row[v] - m);
        out[(long)tb * V_ + v] = e;
        sum += e;
    }
    red[tid] = sum; __syncthreads();
    for (int o = 128; o; o >>= 1) { if (tid < o) red[tid] += red[tid + o]; __syncthreads(); }
    float inv = 1.f / red[0];
    for (int v = tid; v < V_; v += 256) out[(long)tb * V_ + v] *= inv;
}

// ---------------- host ----------------
static inline void launch_gemm(const float* A, int lda, const float* B,
                               const float* bias, float* C, int ldc,
                               int M, int N, int K) {
    dim3 g((N + 63) / 64, (M + 63) / 64);
    sgemm_tn_k<<<g, 256>>>(A, lda, B, bias, C, ldc, M, N, K);
}

extern "C" void kernel_launch(void* const* d_in, const int* in_sizes, int n_in,
                              void* d_out, int out_size) {
    const int*   tv      = (const int*)  d_in[0];   // [T,B]
    const float* h0      = (const float*)d_in[1];   // [1,B,H]
    const float* c0      = (const float*)d_in[2];
    const float* enc     = (const float*)d_in[3];   // [S,B,H]
    const int*   lens    = (const int*)  d_in[4];   // [B]
    const float* emb     = (const float*)d_in[5];   // [V,E]
    const float* W_ih    = (const float*)d_in[6];   // [4H,E]
    const float* W_hh    = (const float*)d_in[7];   // [4H,H]
    const float* b_ih    = (const float*)d_in[8];
    const float* b_hh    = (const float*)d_in[9];
    const float* We      = (const float*)d_in[10];  // [H,H]
    const float* be      = (const float*)d_in[11];
    const float* Wd      = (const float*)d_in[12];
    const float* bd      = (const float*)d_in[13];
    const float* wa      = (const float*)d_in[14];
    const float* ba      = (const float*)d_in[15];
    const float* W_out   = (const float*)d_in[16];  // [V,2H]
    const float* b_out   = (const float*)d_in[17];

    float* scratch = nullptr;
    cudaGetSymbolAddress((void**)&scratch, g_scratch);

    float* s_emb    = scratch + OFF_EMB;
    float* s_xproj  = scratch + OFF_XPROJ;
    float* s_gates  = scratch + OFF_GATES;
    float* s_h      = scratch + OFF_H;
    float* s_c      = scratch + OFF_C;
    float* s_enct   = scratch + OFF_ENCT;
    float* s_dect   = scratch + OFF_DECT;
    float* s_att    = scratch + OFF_ATT;
    float* s_comb   = scratch + OFF_COMB;
    float* s_logits = scratch + OFF_LOGITS;

    float* o_prob = (float*)d_out;                  // [T,B,V]
    float* o_hT   = o_prob + (long)T_ * B_ * V_;    // [1,B,H]
    float* o_cT   = o_hT + B_ * H_;                 // [1,B,H]
    float* o_ctx  = o_cT + B_ * H_;                 // [B,T,H]

    // 1) embedding gather -> [T*B, E]
    gather_emb_k<<<T_ * B_, 128>>>(tv, emb, s_emb);

    // 2) x_proj = emb @ W_ih^T + b_ih : [512, 1024]
    launch_gemm(s_emb, E_, W_ih, b_ih, s_xproj, 4 * H_, T_ * B_, 4 * H_, E_);

    // 3) enc_t = enc @ We^T + be : [8192, 256]
    launch_gemm(enc, H_, We, be, s_enct, H_, S_ * B_, H_, H_);

    // 4) init h, c
    cudaMemcpyAsync(s_h, h0, B_ * H_ * sizeof(float), cudaMemcpyDeviceToDevice);
    cudaMemcpyAsync(s_c, c0, B_ * H_ * sizeof(float), cudaMemcpyDeviceToDevice);

    // 5) LSTM recurrence
    for (int t = 0; t < T_; t++) {
        launch_gemm(s_h, H_, W_hh, nullptr, s_gates, 4 * H_, B_, 4 * H_, H_);
        lstm_point_k<<<B_, H_>>>(s_xproj + (long)t * B_ * 4 * H_, s_gates, b_hh,
                                 s_h, s_c, s_comb + (long)t * B_ * 2 * H_);
    }

    // 6) dec_t = outs @ Wd^T + bd (outs lives in combined[:,:,H:2H], lda=2H)
    launch_gemm(s_comb + H_, 2 * H_, Wd, bd, s_dect, H_, T_ * B_, H_, H_);

    // 7) attention scores, mask+softmax, context
    attn_scores_k<<<T_ * B_, 256>>>(s_enct, s_dect, wa, ba, s_att);
    softmax_att_k<<<B_ * T_, S_>>>(s_att, lens);
    context_k<<<B_ * T_, H_>>>(s_att, enc, s_comb, o_ctx);

    // 8) logits = combined @ W_out^T + b_out : [512, 1000]
    launch_gemm(s_comb, 2 * H_, W_out, b_out, s_logits, V_, T_ * B_, V_, 2 * H_);

    // 9) softmax over V -> output_prob
    softmax_v_k<<<T_ * B_, 256>>>(s_logits, o_prob);

    // 10) final states
    cudaMemcpyAsync(o_hT, s_h, B_ * H_ * sizeof(float), cudaMemcpyDeviceToDevice);
    cudaMemcpyAsync(o_cT, s_c, B_ * H_ * sizeof(float), cudaMemcpyDeviceToDevice);
}

// round 4
// speedup vs baseline: 2.9868x; 2.9868x over previous
#include <cuda_runtime.h>
#include <cuda_bf16.h>
#include <math.h>

#define T_ 16
#define B_ 32
#define S_ 256
#define H_ 256
#define E_ 300
#define V_ 1000

// ---------------- scratch arena (floats) ----------------
#define OFF_EMB     0           // 512*300
#define OFF_XPROJ   153600      // 512*1024
#define OFF_H       710656      // 32*256
#define OFF_ENCT    727040      // 8192*256
#define OFF_DECT    2824192     // 512*256
#define OFF_COMB    3086336     // 512*512
#define OFF_LOGITS  3348480     // 512*1000
#define SCRATCH_N   3860480

__device__ float g_scratch[SCRATCH_N];
__device__ unsigned int g_bar;

// ---------------- embedding gather ----------------
__global__ void gather_emb_k(const int* __restrict__ tv,
                             const float* __restrict__ emb,
                             float* __restrict__ out) {
    int tb = blockIdx.x;
    int v = tv[tb];
    for (int e = threadIdx.x; e < E_; e += blockDim.x)
        out[tb * E_ + e] = emb[v * E_ + e];
}

// ---------------- generic C[M,N] = A[M,K]*B[N,K]^T + bias ----------------
__global__ void sgemm_tn_k(const float* __restrict__ A, int lda,
                           const float* __restrict__ Bm,
                           const float* __restrict__ bias,
                           float* __restrict__ C, int ldc,
                           int M, int N, int K) {
    __shared__ float As[16][64];
    __shared__ float Bs[16][64];
    int tid = threadIdx.x;
    int tx = tid & 15;
    int ty = tid >> 4;
    int m0 = blockIdx.y * 64, n0 = blockIdx.x * 64;
    int row0 = ty * 4, col0 = tx * 4;

    float acc[4][4] = {};
    int lkk = tid & 15;
    int lr0 = tid >> 4;

    for (int k0 = 0; k0 < K; k0 += 16) {
        #pragma unroll
        for (int p = 0; p < 4; p++) {
            int r = lr0 + p * 16;
            int gk = k0 + lkk;
            int gm = m0 + r;
            As[lkk][r] = (gm < M && gk < K) ? A[(long)gm * lda + gk] : 0.f;
            int gn = n0 + r;
            Bs[lkk][r] = (gn < N && gk < K) ? Bm[(long)gn * K + gk] : 0.f;
        }
        __syncthreads();
        #pragma unroll
        for (int kk = 0; kk < 16; kk++) {
            float4 a4 = *reinterpret_cast<const float4*>(&As[kk][row0]);
            float4 b4 = *reinterpret_cast<const float4*>(&Bs[kk][col0]);
            float a[4] = {a4.x, a4.y, a4.z, a4.w};
            float b[4] = {b4.x, b4.y, b4.z, b4.w};
            #pragma unroll
            for (int i = 0; i < 4; i++)
                #pragma unroll
                for (int j = 0; j < 4; j++)
                    acc[i][j] += a[i] * b[j];
        }
        __syncthreads();
    }
    #pragma unroll
    for (int i = 0; i < 4; i++) {
        int gm = m0 + row0 + i;
        if (gm >= M) continue;
        #pragma unroll
        for (int j = 0; j < 4; j++) {
            int gn = n0 + col0 + j;
            if (gn >= N) continue;
            float v = acc[i][j];
            if (bias) v += bias[gn];
            C[(long)gm * ldc + gn] = v;
        }
    }
}

// ---------------- persistent fused LSTM ----------------
// Grid: 64 blocks x 256 threads, all co-resident. Block owns hh in [4*bid, 4*bid+4).
// It computes gate cols {g*256 + hh0 + j : g in 0..3, j in 0..3} (16 cols) for all
// 32 batches each step, does the pointwise update locally (c held in registers),
// writes h to global, grid-syncs, repeats.
#define LSTM_GRID 64
#define HSTRIDE 260   // padded row stride for h_sh (float4-friendly, conflict-free)

__global__ void lstm_persist_k(const float* __restrict__ h0,
                               const float* __restrict__ c0,
                               const float* __restrict__ xproj,   // [T*B, 4H] (has b_ih)
                               const float* __restrict__ W_hh,    // [4H, H]
                               const float* __restrict__ b_hh,    // [4H]
                               float* __restrict__ h_glob,        // [B, H]
                               float* __restrict__ comb,          // [T,B,2H]
                               float* __restrict__ o_hT,
                               float* __restrict__ o_cT) {
    extern __shared__ float sm[];
    float* w_sh = sm;                       // 16*256
    float* h_sh = sm + 16 * 256;            // 32*HSTRIDE
    float* g_sh = h_sh + 32 * HSTRIDE;      // 16*32

    int tid = threadIdx.x, lane = tid & 31, wrp = tid >> 5;
    int hh0 = blockIdx.x * 4;

    // Load the 16 W_hh rows this block owns into smem (once).
    for (int i = tid; i < 16 * 64; i += 256) {
        int lc = i >> 6;                    // local col 0..15
        int kc = i & 63;
        int g = lc >> 2, j = lc & 3;
        int col = g * 256 + hh0 + j;
        reinterpret_cast<float4*>(w_sh)[lc * 64 + kc] =
            reinterpret_cast<const float4*>(W_hh)[col * 64 + kc];
    }

    // c in registers for the pointwise threads (tid<128: j=tid>>5, b=tid&31)
    int pj = tid >> 5, pb = lane;
    float c_reg = 0.f;
    if (tid < 128) c_reg = c0[pb * H_ + hh0 + pj];

    int lc0 = wrp * 2, lc1 = lc0 + 1;
    const float* w0 = w_sh + lc0 * 256;
    const float* w1 = w_sh + lc1 * 256;
    unsigned int bar_t = 0;

    for (int t = 0; t < T_; t++) {
        const float* hsrc = (t == 0) ? h0 : h_glob;
        __syncthreads();
        // stage h[32][256] -> smem (L2-strong loads: written by peer SMs)
        for (int i = tid; i < 2048; i += 256) {          // 2048 float4
            int b = i >> 6, kc = i & 63;
            float4 v = __ldcg(reinterpret_cast<const float4*>(hsrc + b * H_ + kc * 4));
            *reinterpret_cast<float4*>(h_sh + b * HSTRIDE + kc * 4) = v;
        }
        __syncthreads();

        // gates: each warp computes 2 cols for 32 batches (lane = b)
        float acc0 = 0.f, acc1 = 0.f;
        const float* hr = h_sh + lane * HSTRIDE;
        #pragma unroll 8
        for (int k = 0; k < 256; k += 4) {
            float4 hv = *reinterpret_cast<const float4*>(hr + k);
            float4 a4 = *reinterpret_cast<const float4*>(w0 + k);
            float4 b4 = *reinterpret_cast<const float4*>(w1 + k);
            acc0 += hv.x * a4.x + hv.y * a4.y + hv.z * a4.z + hv.w * a4.w;
            acc1 += hv.x * b4.x + hv.y * b4.y + hv.z * b4.z + hv.w * b4.w;
        }
        g_sh[lc0 * 32 + lane] = acc0;
        g_sh[lc1 * 32 + lane] = acc1;
        __syncthreads();

        // pointwise update (exact tanh/sigmoid; only 131k calls total)
        if (tid < 128) {
            int hh = hh0 + pj;
            const float* xp = xproj + (t * B_ + pb) * (4 * H_);
            float gi = g_sh[(0 + pj) * 32 + pb] + xp[hh]            + b_hh[hh];
            float gf = g_sh[(4 + pj) * 32 + pb] + xp[H_ + hh]       + b_hh[H_ + hh];
            float gg = g_sh[(8 + pj) * 32 + pb] + xp[2 * H_ + hh]   + b_hh[2 * H_ + hh];
            float go = g_sh[(12 + pj) * 32 + pb] + xp[3 * H_ + hh]  + b_hh[3 * H_ + hh];
            float si = 1.f / (1.f + __expf(-gi));
            float sf = 1.f / (1.f + __expf(-gf));
            float so = 1.f / (1.f + __expf(-go));
            c_reg = sf * c_reg + si * tanhf(gg);
            float hn = so * tanhf(c_reg);
            h_glob[pb * H_ + hh] = hn;
            comb[(t * B_ + pb) * (2 * H_) + H_ + hh] = hn;
            if (t == T_ - 1) {
                o_hT[pb * H_ + hh] = hn;
                o_cT[pb * H_ + hh] = c_reg;
            }
        }

        // grid sync (skip after final step)
        __syncthreads();
        if (t < T_ - 1) {
            if (tid == 0) {
                __threadfence();
                bar_t += gridDim.x;
                atomicAdd(&g_bar, 1u);
                while (*reinterpret_cast<volatile unsigned int*>(&g_bar) < bar_t) {}
            }
            __syncthreads();
        }
    }
}

// ---------------- fused attention: scores + masked softmax + context ----------------
__device__ __forceinline__ float fast_tanh(float x) {
    float e = __expf(2.f * x);
    return __fdividef(e - 1.f, e + 1.f);
}

__global__ void attn_fused_k(const float* __restrict__ enc_t,  // [S,B,H]
                             const float* __restrict__ dec_t,  // [T,B,H]
                             const float* __restrict__ wa,
                             const float* __restrict__ ba,
                             const int* __restrict__ lens,
                             const float* __restrict__ enc,    // [S,B,H]
                             float* __restrict__ comb,         // [T,B,2H]
                             float* __restrict__ ctx_out) {    // [B,T,H]
    int t = blockIdx.x / B_, b = blockIdx.x % B_;
    __shared__ float dec_sh[H_], wa_sh[H_], sc[S_], red[S_];
    int tid = threadIdx.x;
    dec_sh[tid] = dec_t[(t * B_ + b) * H_ + tid];
    wa_sh[tid] = wa[tid];
    __syncthreads();

    int wrp = tid >> 5, lane = tid & 31;
    float bav = ba[0];
    for (int s = wrp; s < S_; s += 8) {
        const float* er = enc_t + (long)(s * B_ + b) * H_;
        float sum = 0.f;
        #pragma unroll
        for (int i = 0; i < 8; i++) {
            int hh = lane + 32 * i;
            sum += fast_tanh(er[hh] + dec_sh[hh]) * wa_sh[hh];
        }
        #pragma unroll
        for (int o = 16; o; o >>= 1) sum += __shfl_xor_sync(0xffffffffu, sum, o);
        if (lane == 0) sc[s] = sum + bav;
    }
    __syncthreads();

    int len = lens[b];
    float v = (tid < len) ? sc[tid] : -1e30f;
    red[tid] = v; __syncthreads();
    for (int o = 128; o; o >>= 1) { if (tid < o) red[tid] = fmaxf(red[tid], red[tid + o]); __syncthreads(); }
    float m = red[0]; __syncthreads();
    float e = __expf(v - m);
    red[tid] = e; __syncthreads();
    for (int o = 128; o; o >>= 1) { if (tid < o) red[tid] += red[tid + o]; __syncthreads(); }
    float p = e * __fdividef(1.f, red[0]);
    __syncthreads();
    sc[tid] = p;
    __syncthreads();

    // context[b,t,:] = sum_s p[s] * enc[s,b,:]
    float sum = 0.f;
    const float* ep = enc + b * H_ + tid;
    #pragma unroll 4
    for (int s = 0; s < S_; s++)
        sum = fmaf(sc[s], ep[(long)s * B_ * H_], sum);
    comb[(t * B_ + b) * (2 * H_) + tid] = sum;
    ctx_out[(b * T_ + t) * H_ + tid] = sum;
}

// ---------------- softmax over V=1000 ----------------
__global__ void softmax_v_k(const float* __restrict__ logits, float* __restrict__ out) {
    int tb = blockIdx.x;
    int tid = threadIdx.x;
    __shared__ float red[256];
    const float* row = logits + (long)tb * V_;
    float m = -1e30f;
    for (int v = tid; v < V_; v += 256) m = fmaxf(m, row[v]);
    red[tid] = m; __syncthreads();
    for (int o = 128; o; o >>= 1) { if (tid < o) red[tid] = fmaxf(red[tid], red[tid + o]); __syncthreads(); }
    m = red[0]; __syncthreads();
    float sum = 0.f;
    for (int v = tid; v < V_; v += 256) {
        float e = __expf(row[v] - m);
        out[(long)tb * V_ + v] = e;
        sum += e;
    }
    red[tid] = sum; __syncthreads();
    for (int o = 128; o; o >>= 1) { if (tid < o) red[tid] += red[tid + o]; __syncthreads(); }
    float inv = __fdividef(1.f, red[0]);
    for (int v = tid; v < V_; v += 256) out[(long)tb * V_ + v] *= inv;
}

// ---------------- host ----------------
static inline void launch_gemm(const float* A, int lda, const float* B,
                               const float* bias, float* C, int ldc,
                               int M, int N, int K) {
    dim3 g((N + 63) / 64, (M + 63) / 64);
    sgemm_tn_k<<<g, 256>>>(A, lda, B, bias, C, ldc, M, N, K);
}

extern "C" void kernel_launch(void* const* d_in, const int* in_sizes, int n_in,
                              void* d_out, int out_size) {
    const int*   tv      = (const int*)  d_in[0];
    const float* h0      = (const float*)d_in[1];
    const float* c0      = (const float*)d_in[2];
    const float* enc     = (const float*)d_in[3];
    const int*   lens    = (const int*)  d_in[4];
    const float* emb     = (const float*)d_in[5];
    const float* W_ih    = (const float*)d_in[6];
    const float* W_hh    = (const float*)d_in[7];
    const float* b_ih    = (const float*)d_in[8];
    const float* b_hh    = (const float*)d_in[9];
    const float* We      = (const float*)d_in[10];
    const float* be      = (const float*)d_in[11];
    const float* Wd      = (const float*)d_in[12];
    const float* bd      = (const float*)d_in[13];
    const float* wa      = (const float*)d_in[14];
    const float* ba      = (const float*)d_in[15];
    const float* W_out   = (const float*)d_in[16];
    const float* b_out   = (const float*)d_in[17];

    float* scratch = nullptr;
    cudaGetSymbolAddress((void**)&scratch, g_scratch);
    unsigned int* bar = nullptr;
    cudaGetSymbolAddress((void**)&bar, g_bar);

    float* s_emb    = scratch + OFF_EMB;
    float* s_xproj  = scratch + OFF_XPROJ;
    float* s_h      = scratch + OFF_H;
    float* s_enct   = scratch + OFF_ENCT;
    float* s_dect   = scratch + OFF_DECT;
    float* s_comb   = scratch + OFF_COMB;
    float* s_logits = scratch + OFF_LOGITS;

    float* o_prob = (float*)d_out;
    float* o_hT   = o_prob + (long)T_ * B_ * V_;
    float* o_cT   = o_hT + B_ * H_;
    float* o_ctx  = o_cT + B_ * H_;

    // 1) embedding gather -> [T*B, E]
    gather_emb_k<<<T_ * B_, 128>>>(tv, emb, s_emb);

    // 2) x_proj = emb @ W_ih^T + b_ih : [512, 1024]
    launch_gemm(s_emb, E_, W_ih, b_ih, s_xproj, 4 * H_, T_ * B_, 4 * H_, E_);

    // 3) enc_t = enc @ We^T + be : [8192, 256]
    launch_gemm(enc, H_, We, be, s_enct, H_, S_ * B_, H_, H_);

    // 4) persistent LSTM (fused gemm + pointwise, 1 grid-sync/step)
    cudaMemsetAsync(bar, 0, sizeof(unsigned int));
    int lstm_smem = (16 * 256 + 32 * HSTRIDE + 16 * 32) * (int)sizeof(float);
    cudaFuncSetAttribute(lstm_persist_k, cudaFuncAttributeMaxDynamicSharedMemorySize, lstm_smem);
    lstm_persist_k<<<LSTM_GRID, 256, lstm_smem>>>(h0, c0, s_xproj, W_hh, b_hh,
                                                  s_h, s_comb, o_hT, o_cT);

    // 5) dec_t = outs @ Wd^T + bd (outs live in combined[:,:,H:2H], lda=2H)
    launch_gemm(s_comb + H_, 2 * H_, Wd, bd, s_dect, H_, T_ * B_, H_, H_);

    // 6) fused attention scores + masked softmax + context
    attn_fused_k<<<T_ * B_, 256>>>(s_enct, s_dect, wa, ba, lens, enc, s_comb, o_ctx);

    // 7) logits = combined @ W_out^T + b_out : [512, 1000]
    launch_gemm(s_comb, 2 * H_, W_out, b_out, s_logits, V_, T_ * B_, V_, 2 * H_);

    // 8) softmax over V -> output_prob
    softmax_v_k<<<T_ * B_, 256>>>(s_logits, o_prob);
}